// round 4
// baseline (speedup 1.0000x reference)
#include <cuda_runtime.h>
#include <stdint.h>

#define HH 1024
#define WW 1024
#define BB 8
#define CC 3
#define HW (HH*WW)
#define SPITCH 1040
#define SEG 32
#define SEGROWS 32

// scratch (__device__ globals; no allocation allowed)
__device__ float4  g_packed[(size_t)BB*HW];         // (r,g,b,1)  128 MB
__device__ uint8_t g_R[(size_t)BB*HW];              // floor(depth) 8 MB
__device__ float   g_cnt[2u*BB*HW];                 // 64 MB
__device__ float   g_segsum[16*SEG*4*WW];           // 8 MB

// ---------- float4 helpers ----------
__device__ __forceinline__ float4 z4() { return make_float4(0,0,0,0); }
__device__ __forceinline__ float4 f4add(float4 a, float4 b){
    return make_float4(a.x+b.x, a.y+b.y, a.z+b.z, a.w+b.w);
}
__device__ __forceinline__ float4 f4sub(float4 a, float4 b){
    return make_float4(a.x-b.x, a.y-b.y, a.z-b.z, a.w-b.w);
}
__device__ __forceinline__ void f4fma(float4& a, float s, float4 p){
    a.x = fmaf(s, p.x, a.x); a.y = fmaf(s, p.y, a.y);
    a.z = fmaf(s, p.z, a.z); a.w = fmaf(s, p.w, a.w);
}
__device__ __forceinline__ void padd(float4& a, float s,
                                     const float4* __restrict__ pb,
                                     int row, int col) {
    float4 p = __ldg(pb + (size_t)row*WW + col);
    f4fma(a, s, p);
}

__device__ __forceinline__ float4 warp_iscan4(float4 v) {
    int lane = threadIdx.x & 31;
    #pragma unroll
    for (int o = 1; o < 32; o <<= 1) {
        float ax = __shfl_up_sync(0xffffffffu, v.x, o);
        float ay = __shfl_up_sync(0xffffffffu, v.y, o);
        float az = __shfl_up_sync(0xffffffffu, v.z, o);
        float aw = __shfl_up_sync(0xffffffffu, v.w, o);
        if (lane >= o) { v.x += ax; v.y += ay; v.z += az; v.w += aw; }
    }
    return v;
}

// ---------- K0a: pack channels (r,g,b,1) ----------
__global__ __launch_bounds__(256)
void k_pack(const float* __restrict__ image) {
    const size_t i = (size_t)blockIdx.x*1024 + threadIdx.x*4;
    const size_t b = i / HW;
    const size_t o = i - b*HW;
    const float* p = image + b*CC*HW + o;
    float4 r = __ldg((const float4*)(p));
    float4 g = __ldg((const float4*)(p + HW));
    float4 bl= __ldg((const float4*)(p + 2*HW));
    float4* dst = g_packed + i;
    dst[0] = make_float4(r.x, g.x, bl.x, 1.f);
    dst[1] = make_float4(r.y, g.y, bl.y, 1.f);
    dst[2] = make_float4(r.z, g.z, bl.z, 1.f);
    dst[3] = make_float4(r.w, g.w, bl.w, 1.f);
}

// ---------- K0b: depth -> uint8 radius ----------
__global__ __launch_bounds__(256)
void k_r8(const float* __restrict__ depth) {
    const size_t i = (size_t)blockIdx.x*1024 + threadIdx.x*4;
    float4 d = __ldg((const float4*)(depth + i));
    uchar4 v;
    v.x = (uint8_t)(int)d.x; v.y = (uint8_t)(int)d.y;
    v.z = (uint8_t)(int)d.z; v.w = (uint8_t)(int)d.w;
    *(uchar4*)(g_R + i) = v;
}

// ---------- generic border delta (proven path, packed gather) ----------
__device__ void generic_delta(int y, int x, const uint8_t sR[16][SPITCH],
                              const float4* __restrict__ pb,
                              float4& dl, float4& dr) {
    for (int r = 0; r < 8; ++r) {
        const int t0 = (y > 0) ? y + r : 0;
        const int t1 = (y > 0) ? y + r : r;
        const int brow = y - r - 1;
        const int a0 = (x > 0) ? x + 2*r : 0;
        const int a1 = (x > 0) ? x + 2*r : 2*r;
        const int xB = x - 1;
        const int xD = x - 2*r - 1;
        for (int yy = t0; yy <= t1; ++yy) {
            const int idx = yy - y + 8;
            for (int a = a0; a <= a1; ++a)
                if (a < WW && sR[idx][a] == r) padd(dl,  1.f, pb, yy, a);
            if (xB >= 0 && sR[idx][xB] == r)   padd(dl, -1.f, pb, yy, xB);
            if (sR[idx][x] == r)               padd(dr,  1.f, pb, yy, x);
            if (xD >= 0 && sR[idx][xD] == r)   padd(dr, -1.f, pb, yy, xD);
        }
        if (brow >= 0) {
            const int idx = 7 - r;
            for (int a = a0; a <= a1; ++a)
                if (a < WW && sR[idx][a] == r) padd(dl, -1.f, pb, brow, a);
            if (xB >= 0 && sR[idx][xB] == r)   padd(dl,  1.f, pb, brow, xB);
            if (sR[idx][x] == r)               padd(dr, -1.f, pb, brow, x);
            if (xD >= 0 && sR[idx][xD] == r)   padd(dr,  1.f, pb, brow, xD);
        }
    }
}

// ---------- K1: mask-gather + row (x) inclusive scan ----------
__global__ __launch_bounds__(256)
void k_rowscan(float* __restrict__ out) {
    __shared__ uint8_t  sR[16][SPITCH];
    // 4-way column-interleaved source masks: mI[c&3][(c)>>2] for c = col+16
    // bit r    : R(y+r,   col) == r   (top class)
    // bit 8+r  : R(y-r-1, col) == r   (bottom class)
    __shared__ uint32_t mI[4][264];
    __shared__ float4 wtl[8], wtr[8];

    const int y   = blockIdx.x;
    const int b   = blockIdx.y;
    const int t   = threadIdx.x;

    // ---- fill: thread t owns column quad [4t, 4t+3] across all 16 window rows ----
    {
        const uint8_t* rb = g_R + (size_t)b*HW;
        uint32_t mcol0 = 0, mcol1 = 0, mcol2 = 0, mcol3 = 0;
        #pragma unroll
        for (int rr = 0; rr < 16; ++rr) {
            const int ar = y - 8 + rr;
            uchar4 v4 = make_uchar4(255,255,255,255);
            if (ar >= 0 && ar < HH)
                v4 = __ldg((const uchar4*)(rb + (size_t)ar*WW + 4*t));
            *(uchar4*)&sR[rr][4*t] = v4;
            if (rr >= 8) {
                const uint32_t bitc = 1u << (rr - 8);
                if (v4.x == rr - 8) mcol0 |= bitc;
                if (v4.y == rr - 8) mcol1 |= bitc;
                if (v4.z == rr - 8) mcol2 |= bitc;
                if (v4.w == rr - 8) mcol3 |= bitc;
            } else {
                const uint32_t bitc = 1u << (8 + 7 - rr);
                if (v4.x == 7 - rr) mcol0 |= bitc;
                if (v4.y == 7 - rr) mcol1 |= bitc;
                if (v4.z == 7 - rr) mcol2 |= bitc;
                if (v4.w == 7 - rr) mcol3 |= bitc;
            }
        }
        mI[0][t + 4] = mcol0;
        mI[1][t + 4] = mcol1;
        mI[2][t + 4] = mcol2;
        mI[3][t + 4] = mcol3;
        if (t < 4) {
            #pragma unroll
            for (int c = 0; c < 4; ++c) { mI[c][t] = 0u; mI[c][260 + t] = 0u; }
        }
    }
    __syncthreads();

    const float4* pb = g_packed + (size_t)b*HW;

    // hoist this thread's 34-column mask window into registers:
    // msk[j] = mask(col = 4t - 16 + j)
    uint32_t msk[34];
    #pragma unroll
    for (int j = 0; j < 34; ++j)
        msk[j] = mI[j & 3][t + (j >> 2)];

    // 32-bit row offsets (predicated-off when mask bit absent, so OOB rows safe)
    int toff[8], boff[8];
    #pragma unroll
    for (int r = 0; r < 8; ++r) { toff[r] = (y + r) * WW; boff[r] = (y - r - 1) * WW; }

    float4 pl[4], pr[4];
    float4 accl = z4(), accr = z4();

    #pragma unroll
    for (int i = 0; i < 4; ++i) {
        const int x = 4*t + i;
        float4 dl = z4(), dr = z4();

        if (y > 0 && x > 0) {
            const uint32_t mB = msk[i + 15];
            const uint32_t mX = msk[i + 16];
            #pragma unroll
            for (int r = 0; r < 8; ++r) {
                const uint32_t mA = msk[i + 16 + 2*r];
                const uint32_t mD = msk[i + 15 - 2*r];
                const int xA = x + 2*r;
                const int xD = x - 2*r - 1;
                if (mA & (1u <<  r     )) f4fma(dl,  1.f, __ldg(pb + (toff[r] + xA)));
                if (mB & (1u <<  r     )) f4fma(dl, -1.f, __ldg(pb + (toff[r] + x - 1)));
                if (mA & (1u << (8 + r))) f4fma(dl, -1.f, __ldg(pb + (boff[r] + xA)));
                if (mB & (1u << (8 + r))) f4fma(dl,  1.f, __ldg(pb + (boff[r] + x - 1)));
                if (mX & (1u <<  r     )) f4fma(dr,  1.f, __ldg(pb + (toff[r] + x)));
                if (mX & (1u << (8 + r))) f4fma(dr, -1.f, __ldg(pb + (boff[r] + x)));
                if (mD & (1u <<  r     )) f4fma(dr, -1.f, __ldg(pb + (toff[r] + xD)));
                if (mD & (1u << (8 + r))) f4fma(dr,  1.f, __ldg(pb + (boff[r] + xD)));
            }
        } else {
            generic_delta(y, x, sR, pb, dl, dr);
        }
        accl = f4add(accl, dl);  pl[i] = accl;
        accr = f4add(accr, dr);  pr[i] = accr;
    }

    // ---- block-wide inclusive scan along x ----
    const int lane = t & 31, wid = t >> 5;
    float4 tl = pl[3], tr = pr[3];
    float4 il = warp_iscan4(tl);
    float4 ir = warp_iscan4(tr);
    if (lane == 31) { wtl[wid] = il; wtr[wid] = ir; }
    __syncthreads();
    if (t == 0) {
        float4 s = z4();
        #pragma unroll
        for (int w = 0; w < 8; ++w) { float4 tt = wtl[w]; wtl[w] = s; s = f4add(s, tt); }
        s = z4();
        #pragma unroll
        for (int w = 0; w < 8; ++w) { float4 tt = wtr[w]; wtr[w] = s; s = f4add(s, tt); }
    }
    __syncthreads();
    float4 offl = f4add(wtl[wid], f4sub(il, tl));
    float4 offr = f4add(wtr[wid], f4sub(ir, tr));

    float4 rl[4], rr2[4];
    #pragma unroll
    for (int i = 0; i < 4; ++i) { rl[i] = f4add(pl[i], offl); rr2[i] = f4add(pr[i], offr); }

    // ---- stores: cnt (.w) -> g_cnt, channels -> d_out planes ----
    const int vbL = b, vbR = BB + b;
    const size_t rowoff = (size_t)y*WW + 4*t;

    *(float4*)(g_cnt + (size_t)vbL*HW + rowoff) =
        make_float4(rl[0].w, rl[1].w, rl[2].w, rl[3].w);
    *(float4*)(g_cnt + (size_t)vbR*HW + rowoff) =
        make_float4(rr2[0].w, rr2[1].w, rr2[2].w, rr2[3].w);

    float* oL = out + (size_t)vbL*CC*HW + rowoff;
    float* oR = out + (size_t)vbR*CC*HW + rowoff;
    *(float4*)(oL)        = make_float4(rl[0].x, rl[1].x, rl[2].x, rl[3].x);
    *(float4*)(oL + HW)   = make_float4(rl[0].y, rl[1].y, rl[2].y, rl[3].y);
    *(float4*)(oL + 2*HW) = make_float4(rl[0].z, rl[1].z, rl[2].z, rl[3].z);
    *(float4*)(oR)        = make_float4(rr2[0].x, rr2[1].x, rr2[2].x, rr2[3].x);
    *(float4*)(oR + HW)   = make_float4(rr2[0].y, rr2[1].y, rr2[2].y, rr2[3].y);
    *(float4*)(oR + 2*HW) = make_float4(rr2[0].z, rr2[1].z, rr2[2].z, rr2[3].z);
}

// ---------- K2a: per-segment column sums (plane-split) ----------
__global__ __launch_bounds__(256)
void k_colsum(const float* __restrict__ out) {
    const int plane = blockIdx.x;
    const int seg   = blockIdx.y;
    const int vb    = blockIdx.z;
    const int xc    = threadIdx.x * 4;

    const float* src = (plane == 0)
        ? g_cnt + (size_t)vb*HW
        : out + ((size_t)vb*CC + (plane-1))*HW;

    float4 s = z4();
    const int y0 = seg * SEGROWS;
    #pragma unroll 8
    for (int yy = 0; yy < SEGROWS; ++yy)
        s = f4add(s, __ldg((const float4*)(src + (size_t)(y0 + yy)*WW + xc)));

    *(float4*)(g_segsum + (size_t)(((vb*SEG + seg)*4 + plane))*WW + xc) = s;
}

// ---------- K2b: column scan (seeded) + finalize ----------
__global__ __launch_bounds__(256)
void k_colscan_final(float* __restrict__ out) {
    const int seg = blockIdx.y;
    const int vb  = blockIdx.z;
    const int xc  = threadIdx.x * 4;

    float4 r0 = z4(), r1 = z4(), r2 = z4(), r3 = z4();
    for (int s = 0; s < seg; ++s) {
        const float* ss = g_segsum + (size_t)((vb*SEG + s)*4)*WW + xc;
        r0 = f4add(r0, __ldg((const float4*)(ss + 0*WW)));
        r1 = f4add(r1, __ldg((const float4*)(ss + 1*WW)));
        r2 = f4add(r2, __ldg((const float4*)(ss + 2*WW)));
        r3 = f4add(r3, __ldg((const float4*)(ss + 3*WW)));
    }

    const float* p0 = g_cnt + (size_t)vb*HW + xc;
    float* p1 = out + ((size_t)vb*CC + 0)*HW + xc;
    float* p2 = p1 + HW;
    float* p3 = p1 + 2*HW;

    const int y0 = seg * SEGROWS;
    #pragma unroll 2
    for (int yy = 0; yy < SEGROWS; ++yy) {
        const size_t o = (size_t)(y0 + yy)*WW;
        r0 = f4add(r0, __ldg((const float4*)(p0 + o)));
        r1 = f4add(r1, __ldg((const float4*)(p1 + o)));
        r2 = f4add(r2, __ldg((const float4*)(p2 + o)));
        r3 = f4add(r3, __ldg((const float4*)(p3 + o)));

        float4 inv;
        inv.x = __fdividef(1.0f, fmaxf(r0.x, 1.0f));
        inv.y = __fdividef(1.0f, fmaxf(r0.y, 1.0f));
        inv.z = __fdividef(1.0f, fmaxf(r0.z, 1.0f));
        inv.w = __fdividef(1.0f, fmaxf(r0.w, 1.0f));

        *(float4*)(p1 + o) = make_float4(__saturatef(r1.x*inv.x), __saturatef(r1.y*inv.y),
                                         __saturatef(r1.z*inv.z), __saturatef(r1.w*inv.w));
        *(float4*)(p2 + o) = make_float4(__saturatef(r2.x*inv.x), __saturatef(r2.y*inv.y),
                                         __saturatef(r2.z*inv.z), __saturatef(r2.w*inv.w));
        *(float4*)(p3 + o) = make_float4(__saturatef(r3.x*inv.x), __saturatef(r3.y*inv.y),
                                         __saturatef(r3.z*inv.z), __saturatef(r3.w*inv.w));
    }
}

extern "C" void kernel_launch(void* const* d_in, const int* in_sizes, int n_in,
                              void* d_out, int out_size) {
    const float* image = (const float*)d_in[0];   // (8,3,1024,1024) f32
    const float* depth = (const float*)d_in[1];   // (8,1024,1024)   f32
    float* out = (float*)d_out;                   // [left(8,3,H,W), right(8,3,H,W)]

    k_pack<<<BB*HW/1024, 256>>>(image);
    k_r8  <<<BB*HW/1024, 256>>>(depth);
    k_rowscan<<<dim3(HH, BB), 256>>>(out);
    k_colsum<<<dim3(4, SEG, 16), 256>>>(out);
    k_colscan_final<<<dim3(1, SEG, 16), 256>>>(out);
}

// round 5
// speedup vs baseline: 1.2369x; 1.2369x over previous
#include <cuda_runtime.h>
#include <stdint.h>

#define HH 1024
#define WW 1024
#define BB 8
#define CC 3
#define HW (HH*WW)
#define SPITCH 1040
#define SEG 32
#define SEGROWS 32

// scratch (__device__ globals; no allocation allowed)
__device__ float4  g_packed[(size_t)BB*HW];         // (r,g,b,1)  128 MB
__device__ uint8_t g_R[(size_t)BB*HW];              // floor(depth) 8 MB
__device__ float   g_cnt[2u*BB*HW];                 // 64 MB
__device__ float   g_segsum[16*SEG*4*WW];           // 8 MB

// ---------- float4 helpers ----------
__device__ __forceinline__ float4 z4() { return make_float4(0,0,0,0); }
__device__ __forceinline__ float4 f4add(float4 a, float4 b){
    return make_float4(a.x+b.x, a.y+b.y, a.z+b.z, a.w+b.w);
}
__device__ __forceinline__ float4 f4sub(float4 a, float4 b){
    return make_float4(a.x-b.x, a.y-b.y, a.z-b.z, a.w-b.w);
}
__device__ __forceinline__ void f4fma(float4& a, float s, float4 p){
    a.x = fmaf(s, p.x, a.x); a.y = fmaf(s, p.y, a.y);
    a.z = fmaf(s, p.z, a.z); a.w = fmaf(s, p.w, a.w);
}
__device__ __forceinline__ void padd(float4& a, float s,
                                     const float4* __restrict__ pb,
                                     int row, int col) {
    float4 p = __ldg(pb + (size_t)row*WW + col);
    f4fma(a, s, p);
}

__device__ __forceinline__ float4 warp_iscan4(float4 v) {
    int lane = threadIdx.x & 31;
    #pragma unroll
    for (int o = 1; o < 32; o <<= 1) {
        float ax = __shfl_up_sync(0xffffffffu, v.x, o);
        float ay = __shfl_up_sync(0xffffffffu, v.y, o);
        float az = __shfl_up_sync(0xffffffffu, v.z, o);
        float aw = __shfl_up_sync(0xffffffffu, v.w, o);
        if (lane >= o) { v.x += ax; v.y += ay; v.z += az; v.w += aw; }
    }
    return v;
}

// ---------- K0a: pack channels (r,g,b,1) ----------
__global__ __launch_bounds__(256)
void k_pack(const float* __restrict__ image) {
    const size_t i = (size_t)blockIdx.x*1024 + threadIdx.x*4;
    const size_t b = i / HW;
    const size_t o = i - b*HW;
    const float* p = image + b*CC*HW + o;
    float4 r = __ldg((const float4*)(p));
    float4 g = __ldg((const float4*)(p + HW));
    float4 bl= __ldg((const float4*)(p + 2*HW));
    float4* dst = g_packed + i;
    dst[0] = make_float4(r.x, g.x, bl.x, 1.f);
    dst[1] = make_float4(r.y, g.y, bl.y, 1.f);
    dst[2] = make_float4(r.z, g.z, bl.z, 1.f);
    dst[3] = make_float4(r.w, g.w, bl.w, 1.f);
}

// ---------- K0b: depth -> uint8 radius ----------
__global__ __launch_bounds__(256)
void k_r8(const float* __restrict__ depth) {
    const size_t i = (size_t)blockIdx.x*1024 + threadIdx.x*4;
    float4 d = __ldg((const float4*)(depth + i));
    uchar4 v;
    v.x = (uint8_t)(int)d.x; v.y = (uint8_t)(int)d.y;
    v.z = (uint8_t)(int)d.z; v.w = (uint8_t)(int)d.w;
    *(uchar4*)(g_R + i) = v;
}

// ---------- generic border delta (proven path, packed gather) ----------
__device__ void generic_delta(int y, int x, const uint8_t sR[16][SPITCH],
                              const float4* __restrict__ pb,
                              float4& dl, float4& dr) {
    for (int r = 0; r < 8; ++r) {
        const int t0 = (y > 0) ? y + r : 0;
        const int t1 = (y > 0) ? y + r : r;
        const int brow = y - r - 1;
        const int a0 = (x > 0) ? x + 2*r : 0;
        const int a1 = (x > 0) ? x + 2*r : 2*r;
        const int xB = x - 1;
        const int xD = x - 2*r - 1;
        for (int yy = t0; yy <= t1; ++yy) {
            const int idx = yy - y + 8;
            for (int a = a0; a <= a1; ++a)
                if (a < WW && sR[idx][a] == r) padd(dl,  1.f, pb, yy, a);
            if (xB >= 0 && sR[idx][xB] == r)   padd(dl, -1.f, pb, yy, xB);
            if (sR[idx][x] == r)               padd(dr,  1.f, pb, yy, x);
            if (xD >= 0 && sR[idx][xD] == r)   padd(dr, -1.f, pb, yy, xD);
        }
        if (brow >= 0) {
            const int idx = 7 - r;
            for (int a = a0; a <= a1; ++a)
                if (a < WW && sR[idx][a] == r) padd(dl, -1.f, pb, brow, a);
            if (xB >= 0 && sR[idx][xB] == r)   padd(dl,  1.f, pb, brow, xB);
            if (sR[idx][x] == r)               padd(dr, -1.f, pb, brow, x);
            if (xD >= 0 && sR[idx][xD] == r)   padd(dr,  1.f, pb, brow, xD);
        }
    }
}

// ---------- K1: on-demand mask gather + row (x) inclusive scan ----------
__global__ __launch_bounds__(256)
void k_rowscan(float* __restrict__ out) {
    __shared__ uint8_t  sR[16][SPITCH];
    // 4-way column-interleaved source masks; word for shifted col c at mI[c&3][c>>2]
    // (c = col + 16; zero pads at c in [0,16) and [1040,1056))
    // bit r   : R(y+r,   col) == r   (top class)
    // bit 8+r : R(y-r-1, col) == r   (bottom class)
    __shared__ uint32_t mI[4][264];
    __shared__ float4 wtl[8], wtr[8];

    const int y = blockIdx.x;
    const int b = blockIdx.y;
    const int t = threadIdx.x;

    // ---- fill: thread t owns column quad [4t, 4t+3] across all 16 window rows ----
    {
        const uint8_t* rb = g_R + (size_t)b*HW;
        uint32_t mcol0 = 0, mcol1 = 0, mcol2 = 0, mcol3 = 0;
        #pragma unroll
        for (int rr = 0; rr < 16; ++rr) {
            const int ar = y - 8 + rr;
            uchar4 v4 = make_uchar4(255,255,255,255);
            if (ar >= 0 && ar < HH)
                v4 = __ldg((const uchar4*)(rb + (size_t)ar*WW + 4*t));
            *(uchar4*)&sR[rr][4*t] = v4;
            if (rr >= 8) {
                const uint32_t bitc = 1u << (rr - 8);
                if (v4.x == rr - 8) mcol0 |= bitc;
                if (v4.y == rr - 8) mcol1 |= bitc;
                if (v4.z == rr - 8) mcol2 |= bitc;
                if (v4.w == rr - 8) mcol3 |= bitc;
            } else {
                const uint32_t bitc = 1u << (8 + 7 - rr);
                if (v4.x == 7 - rr) mcol0 |= bitc;
                if (v4.y == 7 - rr) mcol1 |= bitc;
                if (v4.z == 7 - rr) mcol2 |= bitc;
                if (v4.w == 7 - rr) mcol3 |= bitc;
            }
        }
        mI[0][t + 4] = mcol0;
        mI[1][t + 4] = mcol1;
        mI[2][t + 4] = mcol2;
        mI[3][t + 4] = mcol3;
        if (t < 4) {
            #pragma unroll
            for (int c = 0; c < 4; ++c) { mI[c][t] = 0u; mI[c][260 + t] = 0u; }
        }
    }
    __syncthreads();

    const float4* pb = g_packed + (size_t)b*HW;

    float4 pl[4], pr[4];
    float4 accl = z4(), accr = z4();

    #pragma unroll 1
    for (int i = 0; i < 4; ++i) {
        const int x = 4*t + i;
        float4 dl = z4(), dr = z4();

        if (y > 0 && x > 0) {
            const int jB = i + 15, jX = i + 16;
            const uint32_t mB = mI[jB & 3][t + (jB >> 2)];
            const uint32_t mX = mI[jX & 3][t + (jX >> 2)];
            #pragma unroll
            for (int r = 0; r < 8; ++r) {
                const int jA = i + 16 + 2*r;
                const int jD = i + 15 - 2*r;
                const uint32_t mA = mI[jA & 3][t + (jA >> 2)];
                const uint32_t mD = mI[jD & 3][t + (jD >> 2)];
                const int to = (y + r) * WW;
                const int bo = (y - r - 1) * WW;
                const int xA = x + 2*r;
                const int xD = x - 2*r - 1;
                if (mA & (1u <<  r     )) f4fma(dl,  1.f, __ldg(pb + (to + xA)));
                if (mB & (1u <<  r     )) f4fma(dl, -1.f, __ldg(pb + (to + x - 1)));
                if (mA & (1u << (8 + r))) f4fma(dl, -1.f, __ldg(pb + (bo + xA)));
                if (mB & (1u << (8 + r))) f4fma(dl,  1.f, __ldg(pb + (bo + x - 1)));
                if (mX & (1u <<  r     )) f4fma(dr,  1.f, __ldg(pb + (to + x)));
                if (mX & (1u << (8 + r))) f4fma(dr, -1.f, __ldg(pb + (bo + x)));
                if (mD & (1u <<  r     )) f4fma(dr, -1.f, __ldg(pb + (to + xD)));
                if (mD & (1u << (8 + r))) f4fma(dr,  1.f, __ldg(pb + (bo + xD)));
            }
        } else {
            generic_delta(y, x, sR, pb, dl, dr);
        }
        accl = f4add(accl, dl);  pl[i] = accl;
        accr = f4add(accr, dr);  pr[i] = accr;
    }

    // ---- block-wide inclusive scan along x ----
    const int lane = t & 31, wid = t >> 5;
    float4 tl = pl[3], tr = pr[3];
    float4 il = warp_iscan4(tl);
    float4 ir = warp_iscan4(tr);
    if (lane == 31) { wtl[wid] = il; wtr[wid] = ir; }
    __syncthreads();
    if (t == 0) {
        float4 s = z4();
        #pragma unroll
        for (int w = 0; w < 8; ++w) { float4 tt = wtl[w]; wtl[w] = s; s = f4add(s, tt); }
        s = z4();
        #pragma unroll
        for (int w = 0; w < 8; ++w) { float4 tt = wtr[w]; wtr[w] = s; s = f4add(s, tt); }
    }
    __syncthreads();
    float4 offl = f4add(wtl[wid], f4sub(il, tl));
    float4 offr = f4add(wtr[wid], f4sub(ir, tr));

    float4 rl[4], rr2[4];
    #pragma unroll
    for (int i = 0; i < 4; ++i) { rl[i] = f4add(pl[i], offl); rr2[i] = f4add(pr[i], offr); }

    // ---- stores: cnt (.w) -> g_cnt, channels -> d_out planes ----
    const int vbL = b, vbR = BB + b;
    const size_t rowoff = (size_t)y*WW + 4*t;

    *(float4*)(g_cnt + (size_t)vbL*HW + rowoff) =
        make_float4(rl[0].w, rl[1].w, rl[2].w, rl[3].w);
    *(float4*)(g_cnt + (size_t)vbR*HW + rowoff) =
        make_float4(rr2[0].w, rr2[1].w, rr2[2].w, rr2[3].w);

    float* oL = out + (size_t)vbL*CC*HW + rowoff;
    float* oR = out + (size_t)vbR*CC*HW + rowoff;
    *(float4*)(oL)        = make_float4(rl[0].x, rl[1].x, rl[2].x, rl[3].x);
    *(float4*)(oL + HW)   = make_float4(rl[0].y, rl[1].y, rl[2].y, rl[3].y);
    *(float4*)(oL + 2*HW) = make_float4(rl[0].z, rl[1].z, rl[2].z, rl[3].z);
    *(float4*)(oR)        = make_float4(rr2[0].x, rr2[1].x, rr2[2].x, rr2[3].x);
    *(float4*)(oR + HW)   = make_float4(rr2[0].y, rr2[1].y, rr2[2].y, rr2[3].y);
    *(float4*)(oR + 2*HW) = make_float4(rr2[0].z, rr2[1].z, rr2[2].z, rr2[3].z);
}

// ---------- K2a: per-segment column sums (plane-split) ----------
__global__ __launch_bounds__(256)
void k_colsum(const float* __restrict__ out) {
    const int plane = blockIdx.x;
    const int seg   = blockIdx.y;
    const int vb    = blockIdx.z;
    const int xc    = threadIdx.x * 4;

    const float* src = (plane == 0)
        ? g_cnt + (size_t)vb*HW
        : out + ((size_t)vb*CC + (plane-1))*HW;

    float4 s = z4();
    const int y0 = seg * SEGROWS;
    #pragma unroll 8
    for (int yy = 0; yy < SEGROWS; ++yy)
        s = f4add(s, __ldg((const float4*)(src + (size_t)(y0 + yy)*WW + xc)));

    *(float4*)(g_segsum + (size_t)(((vb*SEG + seg)*4 + plane))*WW + xc) = s;
}

// ---------- K2b: column scan (seeded) + finalize, x-split for occupancy ----------
__global__ __launch_bounds__(128)
void k_colscan_final(float* __restrict__ out) {
    const int seg = blockIdx.y;
    const int vb  = blockIdx.z;
    const int xc  = blockIdx.x*512 + threadIdx.x*4;

    float4 r0 = z4(), r1 = z4(), r2 = z4(), r3 = z4();
    for (int s = 0; s < seg; ++s) {
        const float* ss = g_segsum + (size_t)((vb*SEG + s)*4)*WW + xc;
        r0 = f4add(r0, __ldg((const float4*)(ss + 0*WW)));
        r1 = f4add(r1, __ldg((const float4*)(ss + 1*WW)));
        r2 = f4add(r2, __ldg((const float4*)(ss + 2*WW)));
        r3 = f4add(r3, __ldg((const float4*)(ss + 3*WW)));
    }

    const float* p0 = g_cnt + (size_t)vb*HW + xc;
    float* p1 = out + ((size_t)vb*CC + 0)*HW + xc;
    float* p2 = p1 + HW;
    float* p3 = p1 + 2*HW;

    const int y0 = seg * SEGROWS;
    #pragma unroll 2
    for (int yy = 0; yy < SEGROWS; ++yy) {
        const size_t o = (size_t)(y0 + yy)*WW;
        r0 = f4add(r0, __ldg((const float4*)(p0 + o)));
        r1 = f4add(r1, __ldg((const float4*)(p1 + o)));
        r2 = f4add(r2, __ldg((const float4*)(p2 + o)));
        r3 = f4add(r3, __ldg((const float4*)(p3 + o)));

        float4 inv;
        inv.x = __fdividef(1.0f, fmaxf(r0.x, 1.0f));
        inv.y = __fdividef(1.0f, fmaxf(r0.y, 1.0f));
        inv.z = __fdividef(1.0f, fmaxf(r0.z, 1.0f));
        inv.w = __fdividef(1.0f, fmaxf(r0.w, 1.0f));

        *(float4*)(p1 + o) = make_float4(__saturatef(r1.x*inv.x), __saturatef(r1.y*inv.y),
                                         __saturatef(r1.z*inv.z), __saturatef(r1.w*inv.w));
        *(float4*)(p2 + o) = make_float4(__saturatef(r2.x*inv.x), __saturatef(r2.y*inv.y),
                                         __saturatef(r2.z*inv.z), __saturatef(r2.w*inv.w));
        *(float4*)(p3 + o) = make_float4(__saturatef(r3.x*inv.x), __saturatef(r3.y*inv.y),
                                         __saturatef(r3.z*inv.z), __saturatef(r3.w*inv.w));
    }
}

extern "C" void kernel_launch(void* const* d_in, const int* in_sizes, int n_in,
                              void* d_out, int out_size) {
    const float* image = (const float*)d_in[0];   // (8,3,1024,1024) f32
    const float* depth = (const float*)d_in[1];   // (8,1024,1024)   f32
    float* out = (float*)d_out;                   // [left(8,3,H,W), right(8,3,H,W)]

    k_pack<<<BB*HW/1024, 256>>>(image);
    k_r8  <<<BB*HW/1024, 256>>>(depth);
    k_rowscan<<<dim3(HH, BB), 256>>>(out);
    k_colsum<<<dim3(4, SEG, 16), 256>>>(out);
    k_colscan_final<<<dim3(2, SEG, 16), 128>>>(out);
}